// round 12
// baseline (speedup 1.0000x reference)
#include <cuda_runtime.h>
#include <cuda_bf16.h>
#include <math.h>
#include <stdint.h>

// Problem constants
#define BATCH  2
#define TSEQ   2048
#define DMODEL 1024
#define NHEADS 16
#define HDIM   64
#define BHTOT  (BATCH * NHEADS)     // 32
#define MROWS  (BATCH * TSEQ)       // 4096
#define KROW   2048                 // hi|lo row stride (bf16)

// ---------------------------------------------------------------------------
// Scratch
// ---------------------------------------------------------------------------
__device__ __nv_bfloat16 g_Qh[(size_t)BHTOT * TSEQ * 128];  // [bh][t][hi64|lo64]
__device__ __nv_bfloat16 g_Kh[(size_t)BHTOT * TSEQ * 128];
__device__ __nv_bfloat16 g_Vh[(size_t)BHTOT * TSEQ * 128];  // [bh][t][hi64|lo64]
__device__ __nv_bfloat16 g_A2[(size_t)MROWS * KROW];      // split activations [hi|lo]
__device__ __nv_bfloat16 g_Bqkv[(size_t)3072 * KROW];     // split Wq|Wk|Wv [hi|lo]
__device__ __nv_bfloat16 g_Bo[(size_t)1024 * KROW];       // split Wo [hi|lo]
__device__ float g_bias_qkv[3072];
__device__ float2 g_trig[TSEQ * 32];                      // cos/sin table [t][d]

// ---------------------------------------------------------------------------
// Helpers
// ---------------------------------------------------------------------------
__device__ __forceinline__ uint32_t smem_u32(const void* p) {
    uint32_t a;
    asm("{ .reg .u64 t; cvta.to.shared.u64 t, %1; cvt.u32.u64 %0, t; }"
        : "=r"(a) : "l"(p));
    return a;
}

#define CP_ASYNC16(sm, gp) \
    asm volatile("cp.async.cg.shared.global [%0], [%1], 16;" :: "r"((uint32_t)(sm)), "l"(gp) : "memory")
#define CP_COMMIT() asm volatile("cp.async.commit_group;" ::: "memory")
#define CP_WAIT(n)  asm volatile("cp.async.wait_group %0;" :: "n"(n) : "memory")

__device__ __forceinline__ void ldsm4(uint32_t* r, uint32_t addr) {
    asm volatile("ldmatrix.sync.aligned.m8n8.x4.shared.b16 {%0,%1,%2,%3}, [%4];"
        : "=r"(r[0]), "=r"(r[1]), "=r"(r[2]), "=r"(r[3]) : "r"(addr));
}

__device__ __forceinline__ void ldsm4t(uint32_t* r, uint32_t addr) {
    asm volatile("ldmatrix.sync.aligned.m8n8.x4.trans.shared.b16 {%0,%1,%2,%3}, [%4];"
        : "=r"(r[0]), "=r"(r[1]), "=r"(r[2]), "=r"(r[3]) : "r"(addr));
}

__device__ __forceinline__ void mma_bf16(float* c, const uint32_t* a, const uint32_t* b) {
    asm volatile(
        "mma.sync.aligned.m16n8k16.row.col.f32.bf16.bf16.f32 "
        "{%0,%1,%2,%3}, {%4,%5,%6,%7}, {%8,%9}, {%0,%1,%2,%3};"
        : "+f"(c[0]), "+f"(c[1]), "+f"(c[2]), "+f"(c[3])
        : "r"(a[0]), "r"(a[1]), "r"(a[2]), "r"(a[3]), "r"(b[0]), "r"(b[1]));
}

__device__ __forceinline__ float ex2f(float x) {
    float r; asm("ex2.approx.f32 %0, %1;" : "=f"(r) : "f"(x)); return r;
}

__device__ __forceinline__ uint32_t packbf2(float a, float b) {
    uint32_t r; asm("cvt.rn.bf16x2.f32 %0, %1, %2;" : "=r"(r) : "f"(b), "f"(a)); return r;
}

// swizzles: 16B-chunk XOR within a row
__device__ __forceinline__ uint32_t swz256(int row, int chunk) {     // 256B rows
    return (uint32_t)(row * 256 + ((chunk ^ (row & 7)) << 4));
}
__device__ __forceinline__ uint32_t swz128(int row, int chunk) {     // 128B rows
    return (uint32_t)(row * 128 + ((chunk ^ (row & 7)) << 4));
}

#define QSCALE (0.125f * 1.44269504088896340736f)

// ---------------------------------------------------------------------------
// trig table: g_trig[t*32+d] = (cos, sin)(t * 10000^{-d/32})
// ---------------------------------------------------------------------------
__global__ void trig_kernel()
{
    int idx = blockIdx.x * blockDim.x + threadIdx.x;   // 65536
    int t = idx >> 5, d = idx & 31;
    float inv_freq = powf(10000.f, -(float)d * (1.f / 32.f));
    float s, c;
    sincosf((float)t * inv_freq, &s, &c);
    g_trig[idx] = make_float2(c, s);
}

// ---------------------------------------------------------------------------
// Fused split: x, Wq, Wk, Wv, Wo -> [hi|lo] bf16 layouts, + bias concat tail.
// ---------------------------------------------------------------------------
__global__ void split_all(const float* __restrict__ x,
                          const float* __restrict__ Wq, const float* __restrict__ Wk,
                          const float* __restrict__ Wv, const float* __restrict__ Wo,
                          const float* __restrict__ bq, const float* __restrict__ bk,
                          const float* __restrict__ bv,
                          __nv_bfloat16* __restrict__ A2,
                          __nv_bfloat16* __restrict__ Bqkv,
                          __nv_bfloat16* __restrict__ Bo)
{
    int bid = blockIdx.x;
    int tid = threadIdx.x;
    if (bid >= 32768) {                       // bias tail: 12 blocks x 256 = 3072
        int i = (bid - 32768) * 256 + tid;
        const float* s = (i < 1024) ? bq : ((i < 2048) ? bk : bv);
        g_bias_qkv[i] = s[i & 1023];
        return;
    }
    int idx = bid * 256 + tid;
    int row = idx >> 10, k = idx & 1023;
    const float* src;
    __nv_bfloat16* dst;
    int lrow;
    if (row < 4096)      { src = x;  dst = A2;                          lrow = row; }
    else if (row < 5120) { src = Wq; dst = Bqkv;                        lrow = row - 4096; }
    else if (row < 6144) { src = Wk; dst = Bqkv + (size_t)1024 * KROW;  lrow = row - 5120; }
    else if (row < 7168) { src = Wv; dst = Bqkv + (size_t)2048 * KROW;  lrow = row - 6144; }
    else                 { src = Wo; dst = Bo;                          lrow = row - 7168; }
    float v = src[(size_t)lrow * 1024 + k];
    __nv_bfloat16 hi = __float2bfloat16(v);
    __nv_bfloat16 lo = __float2bfloat16(v - __bfloat162float(hi));
    size_t base = (size_t)lrow * KROW;
    dst[base + k] = hi;
    dst[base + 1024 + k] = lo;
}

// ---------------------------------------------------------------------------
// HMMA bf16 GEMM: C = x @ W^T + bias via 3-term split over [hi|lo] layout.
// mode 0: fp32 row-major out.
// mode 1: QKV — Q/K get fused RoPE (+QSCALE for Q) and bf16 [hi|lo] to
//         g_Qh/g_Kh; V gets bias + bf16 [hi|lo] to g_Vh (same layout as K).
// ---------------------------------------------------------------------------
#define GNS 48
#define GSTG 3
#define GEMM_SMEM (GSTG * 2 * 128 * 128)   // 98304

__global__ __launch_bounds__(256, 2) void gemm_hmma(
    const __nv_bfloat16* __restrict__ A2, const __nv_bfloat16* __restrict__ B2,
    const float* __restrict__ bias, float* __restrict__ out0, int mode)
{
    extern __shared__ __align__(128) char gsm[];
    const uint32_t base = smem_u32(gsm);

    const int tid = threadIdx.x;
    const int lane = tid & 31;
    const int wid = tid >> 5;
    const int warp_m = wid & 3;
    const int warp_n = wid >> 2;
    const int m0 = blockIdx.y * 128;
    const int n0 = blockIdx.x * 128;

    uint32_t sbA[GSTG], sbB[GSTG];
#pragma unroll
    for (int i = 0; i < GSTG; i++) {
        sbA[i] = base + i * 32768;
        sbB[i] = base + i * 32768 + 16384;
    }

    const __nv_bfloat16* Abase = A2 + (size_t)m0 * KROW;
    const __nv_bfloat16* Bbase = B2 + (size_t)n0 * KROW;

    float acc[2][8][4];
#pragma unroll
    for (int i = 0; i < 2; i++)
#pragma unroll
        for (int j = 0; j < 8; j++)
#pragma unroll
            for (int q = 0; q < 4; q++) acc[i][j][q] = 0.f;

    auto load_stage = [&](int s) {
        int b = s % GSTG;
        int term = s >> 4, sub = s & 15;
        int aoff = ((term == 1) ? 1024 : 0) + sub * 64;
        int boff = ((term == 2) ? 1024 : 0) + sub * 64;
        const __nv_bfloat16* Ag = Abase + aoff;
        const __nv_bfloat16* Bg = Bbase + boff;
#pragma unroll
        for (int u = 0; u < 4; u++) {
            int flat = tid + u * 256;            // 0..1023
            int r = flat >> 3, c = flat & 7;
            uint32_t off = swz128(r, c);
            CP_ASYNC16(sbA[b] + off, (const void*)(Ag + (size_t)r * KROW + c * 8));
            CP_ASYNC16(sbB[b] + off, (const void*)(Bg + (size_t)r * KROW + c * 8));
        }
        CP_COMMIT();
    };

    load_stage(0);
    load_stage(1);

    for (int s = 0; s < GNS; s++) {
        int b = s % GSTG;
        if (s < GNS - 1) { CP_WAIT(1); } else { CP_WAIT(0); }
        __syncthreads();

#pragma unroll
        for (int kk = 0; kk < 4; kk++) {
            uint32_t af[2][4];
#pragma unroll
            for (int tm = 0; tm < 2; tm++) {
                int row = warp_m * 32 + tm * 16 + (lane & 7) + ((lane >> 3) & 1) * 8;
                int chunk = kk * 2 + (lane >> 4);
                ldsm4(af[tm], sbA[b] + swz128(row, chunk));
            }
            uint32_t bf[4][4];
#pragma unroll
            for (int p = 0; p < 4; p++) {
                int row = warp_n * 64 + p * 16 + (lane & 7) + (lane >> 4) * 8;
                int chunk = kk * 2 + ((lane >> 3) & 1);
                ldsm4(bf[p], sbB[b] + swz128(row, chunk));
            }
#pragma unroll
            for (int tm = 0; tm < 2; tm++)
#pragma unroll
                for (int tn = 0; tn < 8; tn++)
                    mma_bf16(acc[tm][tn], af[tm], &bf[tn >> 1][(tn & 1) * 2]);
        }

        if (s + 2 < GNS) load_stage(s + 2);
    }

    const int m_base = m0 + warp_m * 32;
    const int n_base = n0 + warp_n * 64;

    if (mode == 0) {
#pragma unroll
        for (int tm = 0; tm < 2; tm++) {
#pragma unroll
            for (int tn = 0; tn < 8; tn++) {
                int r0 = m_base + tm * 16 + (lane >> 2);
                int c0 = n_base + tn * 8 + 2 * (lane & 3);
                float bx = bias[c0], by = bias[c0 + 1];
#pragma unroll
                for (int half = 0; half < 2; half++) {
                    int m = r0 + half * 8;
                    float2* dst = (float2*)(out0 + (size_t)m * 1024 + c0);
                    *dst = make_float2(acc[tm][tn][half * 2 + 0] + bx,
                                       acc[tm][tn][half * 2 + 1] + by);
                }
            }
        }
        return;
    }

    // mode 1: which third (Q/K/V) — constant per warp (64-col span = 1 head)
    const int which = n_base >> 10;
    const int head = (n_base & 1023) >> 6;

    if (which == 2) {
        // V: bias + bf16 [hi|lo] split into g_Vh (same layout as K)
#pragma unroll
        for (int tm = 0; tm < 2; tm++) {
#pragma unroll
            for (int tn = 0; tn < 8; tn++) {
                int c0 = n_base + tn * 8 + 2 * (lane & 3);
                int d = c0 & 63;                     // even
                float bx = bias[c0], by = bias[c0 + 1];
#pragma unroll
                for (int half = 0; half < 2; half++) {
                    int m = m_base + tm * 16 + (lane >> 2) + half * 8;
                    int bb2 = m >> 11;
                    int t = m & (TSEQ - 1);
                    float o0 = acc[tm][tn][half * 2 + 0] + bx;
                    float o1 = acc[tm][tn][half * 2 + 1] + by;
                    float h0 = __bfloat162float(__float2bfloat16(o0));
                    float h1 = __bfloat162float(__float2bfloat16(o1));
                    size_t ob = (((size_t)(bb2 * NHEADS + head)) * TSEQ + t) * 128;
                    *(uint32_t*)(g_Vh + ob + d)      = packbf2(o0, o1);
                    *(uint32_t*)(g_Vh + ob + 64 + d) = packbf2(o0 - h0, o1 - h1);
                }
            }
        }
    } else {
        // Q or K: fused RoPE (+QSCALE for Q) + bf16 hi/lo split
        __nv_bfloat16* dstb = (which == 0) ? g_Qh : g_Kh;
        const float scale = (which == 0) ? QSCALE : 1.f;
#pragma unroll
        for (int tm = 0; tm < 2; tm++) {
#pragma unroll
            for (int tn = 0; tn < 4; tn++) {
                int c0 = n_base + tn * 8 + 2 * (lane & 3);
                int d = c0 & 31;                     // even, partner at d+32
                float b1x = bias[c0],      b1y = bias[c0 + 1];
                float b2x = bias[c0 + 32], b2y = bias[c0 + 33];
#pragma unroll
                for (int half = 0; half < 2; half++) {
                    int m = m_base + tm * 16 + (lane >> 2) + half * 8;
                    int bb2 = m >> 11;
                    int t = m & (TSEQ - 1);
                    float2 cs0 = g_trig[(t << 5) + d];
                    float2 cs1 = g_trig[(t << 5) + d + 1];
                    float q1x = acc[tm][tn][half * 2 + 0] + b1x;
                    float q1y = acc[tm][tn][half * 2 + 1] + b1y;
                    float q2x = acc[tm][tn + 4][half * 2 + 0] + b2x;
                    float q2y = acc[tm][tn + 4][half * 2 + 1] + b2y;
                    float o1x = (q1x * cs0.x - q2x * cs0.y) * scale;
                    float o2x = (q2x * cs0.x + q1x * cs0.y) * scale;
                    float o1y = (q1y * cs1.x - q2y * cs1.y) * scale;
                    float o2y = (q2y * cs1.x + q1y * cs1.y) * scale;
                    float h1x = __bfloat162float(__float2bfloat16(o1x));
                    float h1y = __bfloat162float(__float2bfloat16(o1y));
                    float h2x = __bfloat162float(__float2bfloat16(o2x));
                    float h2y = __bfloat162float(__float2bfloat16(o2y));
                    size_t ob = (((size_t)(bb2 * NHEADS + head)) * TSEQ + t) * 128;
                    *(uint32_t*)(dstb + ob + d)      = packbf2(o1x, o1y);
                    *(uint32_t*)(dstb + ob + 32 + d) = packbf2(o2x, o2y);
                    *(uint32_t*)(dstb + ob + 64 + d) = packbf2(o1x - h1x, o1y - h1y);
                    *(uint32_t*)(dstb + ob + 96 + d) = packbf2(o2x - h2x, o2y - h2y);
                }
            }
        }
    }
}

// ---------------------------------------------------------------------------
// HMMA flash attention. V now stored [t][hi64|lo64] like K; PV B-fragments
// come from ldmatrix.x4.trans (FA2-style), so no V transpose pass exists.
// ---------------------------------------------------------------------------
#define AQ 128
#define AK 64
#define NKT (TSEQ / AK)   // 32
#define ATTN_SMEM 98304

__global__ __launch_bounds__(128) void attn_mma(
    const __nv_bfloat16* __restrict__ Qh, const __nv_bfloat16* __restrict__ Kh,
    const __nv_bfloat16* __restrict__ Vh, __nv_bfloat16* __restrict__ A2)
{
    extern __shared__ __align__(128) char smem[];
    const uint32_t sQ = smem_u32(smem);
    const uint32_t sK[2] = { sQ + 32768, sQ + 32768 + 16384 };
    const uint32_t sV[2] = { sQ + 65536, sQ + 65536 + 16384 };

    const int tid = threadIdx.x, lane = tid & 31, wid = tid >> 5;
    const int qtile = blockIdx.x, bh = blockIdx.y;

    const __nv_bfloat16* Qg = Qh + ((size_t)bh * TSEQ + qtile * AQ) * 128;
    const __nv_bfloat16* Kg = Kh + (size_t)bh * TSEQ * 128;
    const __nv_bfloat16* Vg = Vh + (size_t)bh * TSEQ * 128;

    auto loadKV = [&](int t) {
        int b = t & 1;
        const __nv_bfloat16* Kt = Kg + (size_t)t * AK * 128;
        const __nv_bfloat16* Vt = Vg + (size_t)t * AK * 128;
#pragma unroll
        for (int u = 0; u < 8; u++) {
            int flat = tid + u * 128;          // 0..1023
            int r = flat >> 4, c = flat & 15;
            uint32_t off = swz256(r, c);
            CP_ASYNC16(sK[b] + off, (const void*)(Kt + r * 128 + c * 8));
            CP_ASYNC16(sV[b] + off, (const void*)(Vt + r * 128 + c * 8));
        }
    };

#pragma unroll
    for (int u = 0; u < 16; u++) {
        int flat = tid + u * 128;
        int r = flat >> 4, c = flat & 15;
        CP_ASYNC16(sQ + swz256(r, c), (const void*)(Qg + r * 128 + c * 8));
    }
    loadKV(0);
    CP_COMMIT();

    float O[2][8][4];
#pragma unroll
    for (int i = 0; i < 2; i++)
#pragma unroll
        for (int j = 0; j < 8; j++)
#pragma unroll
            for (int q = 0; q < 4; q++) O[i][j][q] = 0.f;
    float mrow[2][2] = { {-1e30f, -1e30f}, {-1e30f, -1e30f} };
    float lrow[2][2] = { {0.f, 0.f}, {0.f, 0.f} };

    for (int t = 0; t < NKT; t++) {
        int b = t & 1;
        if (t + 1 < NKT) { loadKV(t + 1); CP_COMMIT(); CP_WAIT(1); }
        else { CP_WAIT(0); }
        __syncthreads();

        float S[2][8][4];
#pragma unroll
        for (int i = 0; i < 2; i++)
#pragma unroll
            for (int j = 0; j < 8; j++)
#pragma unroll
                for (int q = 0; q < 4; q++) S[i][j][q] = 0.f;

        // ---- QK phase A: K_hi with Q_hi and Q_lo ----
#pragma unroll
        for (int kk = 0; kk < 4; kk++) {
            uint32_t bf4[4][4];
#pragma unroll
            for (int p = 0; p < 4; p++) {
                int row = p * 16 + (lane & 7) + (lane >> 4) * 8;
                int chunk = kk * 2 + ((lane >> 3) & 1);
                ldsm4(bf4[p], sK[b] + swz256(row, chunk));
            }
            uint32_t afh[2][4], afl[2][4];
#pragma unroll
            for (int tm = 0; tm < 2; tm++) {
                int row = wid * 32 + tm * 16 + (lane & 7) + ((lane >> 3) & 1) * 8;
                int chunk = kk * 2 + (lane >> 4);
                ldsm4(afh[tm], sQ + swz256(row, chunk));
                ldsm4(afl[tm], sQ + swz256(row, 8 + chunk));
            }
#pragma unroll
            for (int tm = 0; tm < 2; tm++)
#pragma unroll
                for (int tn = 0; tn < 8; tn++) {
                    const uint32_t* bb = &bf4[tn >> 1][(tn & 1) * 2];
                    mma_bf16(S[tm][tn], afh[tm], bb);
                    mma_bf16(S[tm][tn], afl[tm], bb);
                }
        }
        // ---- QK phase B: K_lo with Q_hi ----
#pragma unroll
        for (int kk = 0; kk < 4; kk++) {
            uint32_t bf4[4][4];
#pragma unroll
            for (int p = 0; p < 4; p++) {
                int row = p * 16 + (lane & 7) + (lane >> 4) * 8;
                int chunk = 8 + kk * 2 + ((lane >> 3) & 1);
                ldsm4(bf4[p], sK[b] + swz256(row, chunk));
            }
            uint32_t afh[2][4];
#pragma unroll
            for (int tm = 0; tm < 2; tm++) {
                int row = wid * 32 + tm * 16 + (lane & 7) + ((lane >> 3) & 1) * 8;
                int chunk = kk * 2 + (lane >> 4);
                ldsm4(afh[tm], sQ + swz256(row, chunk));
            }
#pragma unroll
            for (int tm = 0; tm < 2; tm++)
#pragma unroll
                for (int tn = 0; tn < 8; tn++)
                    mma_bf16(S[tm][tn], afh[tm], &bf4[tn >> 1][(tn & 1) * 2]);
        }

        // ---- online softmax (exp2 domain) + P pack ----
        uint32_t Ppk[2][2][16];
#pragma unroll
        for (int tm = 0; tm < 2; tm++) {
#pragma unroll
            for (int rh = 0; rh < 2; rh++) {
                float mx = S[tm][0][rh * 2];
#pragma unroll
                for (int tn = 0; tn < 8; tn++) {
                    mx = fmaxf(mx, S[tm][tn][rh * 2 + 0]);
                    mx = fmaxf(mx, S[tm][tn][rh * 2 + 1]);
                }
                mx = fmaxf(mx, __shfl_xor_sync(0xffffffffu, mx, 1));
                mx = fmaxf(mx, __shfl_xor_sync(0xffffffffu, mx, 2));
                float mold = mrow[tm][rh];
                float mnew = fmaxf(mold, mx);
                float corr = ex2f(mold - mnew);
                mrow[tm][rh] = mnew;
                float rsum = 0.f;
#pragma unroll
                for (int tn = 0; tn < 8; tn++) {
                    float p0 = ex2f(S[tm][tn][rh * 2 + 0] - mnew);
                    float p1 = ex2f(S[tm][tn][rh * 2 + 1] - mnew);
                    rsum += p0 + p1;
                    float h0 = __bfloat162float(__float2bfloat16(p0));
                    float h1 = __bfloat162float(__float2bfloat16(p1));
                    Ppk[tm][0][tn * 2 + rh] = packbf2(p0, p1);
                    Ppk[tm][1][tn * 2 + rh] = packbf2(p0 - h0, p1 - h1);
                    O[tm][tn][rh * 2 + 0] *= corr;
                    O[tm][tn][rh * 2 + 1] *= corr;
                }
                rsum += __shfl_xor_sync(0xffffffffu, rsum, 1);
                rsum += __shfl_xor_sync(0xffffffffu, rsum, 2);
                lrow[tm][rh] = lrow[tm][rh] * corr + rsum;
            }
        }

        // ---- PV phase A: V_hi (trans-ldsm) with P_hi and P_lo ----
#pragma unroll
        for (int kk = 0; kk < 4; kk++) {
            uint32_t bfv[4][4];
#pragma unroll
            for (int p = 0; p < 4; p++) {
                int trow = kk * 16 + (lane & 7) + ((lane >> 3) & 1) * 8;
                int chunk = p * 2 + (lane >> 4);
                ldsm4t(bfv[p], sV[b] + swz256(trow, chunk));
            }
#pragma unroll
            for (int tm = 0; tm < 2; tm++)
#pragma unroll
                for (int tn = 0; tn < 8; tn++) {
                    const uint32_t* bb = &bfv[tn >> 1][(tn & 1) * 2];
                    mma_bf16(O[tm][tn], &Ppk[tm][0][4 * kk], bb);
                    mma_bf16(O[tm][tn], &Ppk[tm][1][4 * kk], bb);
                }
        }
        // ---- PV phase B: V_lo (trans-ldsm) with P_hi ----
#pragma unroll
        for (int kk = 0; kk < 4; kk++) {
            uint32_t bfv[4][4];
#pragma unroll
            for (int p = 0; p < 4; p++) {
                int trow = kk * 16 + (lane & 7) + ((lane >> 3) & 1) * 8;
                int chunk = 8 + p * 2 + (lane >> 4);
                ldsm4t(bfv[p], sV[b] + swz256(trow, chunk));
            }
#pragma unroll
            for (int tm = 0; tm < 2; tm++)
#pragma unroll
                for (int tn = 0; tn < 8; tn++)
                    mma_bf16(O[tm][tn], &Ppk[tm][0][4 * kk],
                             &bfv[tn >> 1][(tn & 1) * 2]);
        }
        __syncthreads();
    }

    // ---- epilogue: write split ctx [hi|lo] into A2 ----
    const int bb = bh >> 4, h = bh & 15;
#pragma unroll
    for (int tm = 0; tm < 2; tm++) {
#pragma unroll
        for (int rh = 0; rh < 2; rh++) {
            float inv = 1.f / lrow[tm][rh];
            int trow = qtile * AQ + wid * 32 + tm * 16 + rh * 8 + (lane >> 2);
            size_t m = (size_t)bb * TSEQ + trow;
            __nv_bfloat16* rowp = A2 + m * KROW + h * 64;
#pragma unroll
            for (int tn = 0; tn < 8; tn++) {
                float o0 = O[tm][tn][rh * 2 + 0] * inv;
                float o1 = O[tm][tn][rh * 2 + 1] * inv;
                int d = tn * 8 + (lane & 3) * 2;
                uint32_t hi2 = packbf2(o0, o1);
                float h0 = __bfloat162float(__float2bfloat16(o0));
                float h1 = __bfloat162float(__float2bfloat16(o1));
                uint32_t lo2 = packbf2(o0 - h0, o1 - h1);
                *(uint32_t*)(rowp + d) = hi2;
                *(uint32_t*)(rowp + 1024 + d) = lo2;
            }
        }
    }
}

// ---------------------------------------------------------------------------
// Launch
// ---------------------------------------------------------------------------
extern "C" void kernel_launch(void* const* d_in, const int* in_sizes, int n_in,
                              void* d_out, int out_size)
{
    const float* x  = (const float*)d_in[0];
    const float* Wq = (const float*)d_in[1];
    const float* bq = (const float*)d_in[2];
    const float* Wk = (const float*)d_in[3];
    const float* bk = (const float*)d_in[4];
    const float* Wv = (const float*)d_in[5];
    const float* bv = (const float*)d_in[6];
    const float* Wo = (const float*)d_in[7];
    const float* bo = (const float*)d_in[8];
    float* out = (float*)d_out;

    float *BIp;
    __nv_bfloat16 *A2p, *Bqkvp, *Bop, *Qhp, *Khp, *Vhp;
    cudaGetSymbolAddress((void**)&A2p, g_A2);
    cudaGetSymbolAddress((void**)&Bqkvp, g_Bqkv);
    cudaGetSymbolAddress((void**)&Bop, g_Bo);
    cudaGetSymbolAddress((void**)&BIp, g_bias_qkv);
    cudaGetSymbolAddress((void**)&Qhp, g_Qh);
    cudaGetSymbolAddress((void**)&Khp, g_Kh);
    cudaGetSymbolAddress((void**)&Vhp, g_Vh);

    cudaFuncSetAttribute(attn_mma, cudaFuncAttributeMaxDynamicSharedMemorySize, ATTN_SMEM);
    cudaFuncSetAttribute(gemm_hmma, cudaFuncAttributeMaxDynamicSharedMemorySize, GEMM_SMEM);

    // trig table + fused split conversions (+ bias concat tail blocks)
    trig_kernel<<<TSEQ * 32 / 256, 256>>>();
    split_all<<<32768 + 12, 256>>>(x, Wq, Wk, Wv, Wo, bq, bk, bv, A2p, Bqkvp, Bop);

    // fused QKV projection + RoPE + bf16 split (Q,K,V all direct)
    gemm_hmma<<<dim3(3072 / 128, MROWS / 128), 256, GEMM_SMEM>>>(
        A2p, Bqkvp, BIp, nullptr, 1);

    // HMMA flash attention -> split ctx in g_A2
    attn_mma<<<dim3(TSEQ / AQ, BHTOT), 128, ATTN_SMEM>>>(Qhp, Khp, Vhp, A2p);

    // output projection -> d_out
    gemm_hmma<<<dim3(1024 / 128, MROWS / 128), 256, GEMM_SMEM>>>(
        A2p, Bop, bo, out, 0);

    (void)in_sizes; (void)n_in; (void)out_size;
}